// round 16
// baseline (speedup 1.0000x reference)
#include <cuda_runtime.h>
#include <cuda_bf16.h>
#include <math.h>

// ---------------- Problem constants ----------------
#define NREF 131072
#define NALT 32768
#define BSEG 4096
#define DDIM 128
#define FDIM 512
#define HDIM 256
#define LN_EPS 1e-5f

typedef unsigned int u32;

// ---------------- Scratch (device globals) ----------------
__device__ u32 g_z1_ref[(size_t)NREF * 128];   // bf16x2 pairs (256 cols)
__device__ u32 g_z2_ref[(size_t)NREF * 128];
__device__ u32 g_z1_alt[(size_t)NALT * 128];
__device__ u32 g_z2_alt[(size_t)NALT * 128];
__device__ float g_sum_ref[BSEG * HDIM];       // zero-init at load; coeff re-zeros
__device__ float g_sum_alt[BSEG * HDIM];
__device__ float g_cnt_ref[BSEG];
__device__ float g_cnt_alt[BSEG];
__device__ float g_cref[BSEG * HDIM];
__device__ float g_calt[BSEG * HDIM];

// ---------------- Helpers ----------------
__device__ __forceinline__ u32 pkbf(float lo, float hi) {
    u32 r;
    asm("cvt.rn.bf16x2.f32 %0, %1, %2;" : "=r"(r) : "f"(hi), "f"(lo));
    return r;
}
__device__ __forceinline__ float2 upbf(u32 v) {
    union { u32 u; __nv_bfloat162 h; } cv;
    cv.u = v;
    return __bfloat1622float2(cv.h);
}
__device__ __forceinline__ void mma_bf16(float* c, const u32* a, u32 b0, u32 b1) {
    asm volatile(
        "mma.sync.aligned.m16n8k16.row.col.f32.bf16.bf16.f32 "
        "{%0,%1,%2,%3}, {%4,%5,%6,%7}, {%8,%9}, {%0,%1,%2,%3};"
        : "+f"(c[0]), "+f"(c[1]), "+f"(c[2]), "+f"(c[3])
        : "r"(a[0]), "r"(a[1]), "r"(a[2]), "r"(a[3]), "r"(b0), "r"(b1));
}
__device__ __forceinline__ u32 s2u(const void* p) {
    return (u32)__cvta_generic_to_shared(p);
}
__device__ __forceinline__ void cp16(u32 smem_dst, const void* gsrc) {
    asm volatile("cp.async.cg.shared.global [%0], [%1], 16;"
                 :: "r"(smem_dst), "l"(gsrc));
}
__device__ __forceinline__ void cp_commit() {
    asm volatile("cp.async.commit_group;");
}
__device__ __forceinline__ void cp_wait0() {
    asm volatile("cp.async.wait_group 0;");
}
__device__ __forceinline__ void pf_l2(const void* p) {
    asm volatile("prefetch.global.L2 [%0];" :: "l"(p));
}
__device__ __forceinline__ float warp_sum(float v) {
#pragma unroll
    for (int o = 16; o > 0; o >>= 1) v += __shfl_xor_sync(0xffffffffu, v, o);
    return v;
}

// SELU with MUFU-free exp: 2^t split (floor + degree-5 poly on FMA pipe +
// integer exponent reconstruction). Rel err ~1.5e-5 << bf16 rounding of z.
__device__ __forceinline__ float selu_f(float x) {
    const float sc = 1.0507009873554805f;
    const float al = 1.6732632423543772f;
    float t = fmaxf(x * 1.4426950408889634f, -126.0f);
    float fl = floorf(t);
    float f = t - fl;
    float p =            1.3333558146e-3f;
    p = fmaf(p, f, 9.6181291076e-3f);
    p = fmaf(p, f, 5.5504108664e-2f);
    p = fmaf(p, f, 2.4022650695e-1f);
    p = fmaf(p, f, 6.9314718056e-1f);
    p = fmaf(p, f, 1.0f);
    float e2 = __int_as_float(((int)fl + 127) << 23);
    float ex = p * e2;
    return x > 0.f ? sc * x : fmaf(sc * al, ex, -(sc * al));
}

// ---------------- Kernel 1: split-class persistent LN1+GEMM1 --------------
// 2 CTAs/SM. Even blocks: z1 half. Odd blocks: z2 half + LN2 + segsum.
// sz stride 132 (uint4-aligned flushes). x: cp.async d1 + L2 prefetch d2.
#define SW1_U (256 * 68)
#define SA_U  (32 * 68)
#define SZ_U  (32 * 132)
#define SX_U  (32 * 132)
#define SM1_BYTES ((SW1_U + SA_U + SZ_U + SX_U + 32 * 8 * 2) * 4 + 32 * 4)

__global__ void __launch_bounds__(512, 2)
fwd1_kernel(const float* __restrict__ x, const int* __restrict__ seg,
            const float* __restrict__ n1w, const float* __restrict__ n1b,
            const float* __restrict__ w1, const float* __restrict__ b1,
            const float* __restrict__ n2w, const float* __restrict__ n2b,
            u32* __restrict__ z1out, u32* __restrict__ z2out,
            float* __restrict__ segsum, float* __restrict__ segcnt,
            int ntiles) {
    extern __shared__ float smf[];
    u32* sw = (u32*)smf;              // [256 n][68] bf16 k-pairs of W1 half
    u32* sa = sw + SW1_U;             // [32 m][68]  bf16 k-pairs of LN1(x)
    u32* sz = sa + SA_U;              // [32 m][132] bf16 col-pairs staging
    float* sx = (float*)(sz + SZ_U);  // [32 m][132] prefetched x (f32)
    float* ps = sx + SX_U;            // [32][8] LN2 partial sums
    float* pq = ps + 32 * 8;          // [32][8] LN2 partial sumsq
    int*   ssg = (int*)(pq + 32 * 8); // [32]

    const int zcls = blockIdx.x & 1;       // 0 -> z1 half, 1 -> z2 half
    const int bidc = blockIdx.x >> 1;
    const int nblk = gridDim.x >> 1;

    const int tid = threadIdx.x;
    const int lane = tid & 31;
    const int wid = tid >> 5;
    const int g = lane >> 2;
    const int t = lane & 3;
    const int wm = wid & 1;    // 2 row-groups of 16
    const int wn = wid >> 1;   // 8 col-groups of 32

    // ---- stage this class's W1 half (f32 gmem -> bf16-pair smem), once
    for (int i = tid; i < 64 * 256; i += 512) {
        int kp = i >> 8;
        int n = i & 255;
        float v0 = __ldg(w1 + (size_t)(2 * kp) * FDIM + zcls * 256 + n);
        float v1 = __ldg(w1 + (size_t)(2 * kp + 1) * FDIM + zcls * 256 + n);
        sw[n * 68 + kp] = pkbf(v0, v1);
    }

    // ---- hoist per-thread constants
    float4 wv = __ldg(((const float4*)n1w) + lane);
    float4 bv = __ldg(((const float4*)n1b) + lane);
    float b1r[4][2], w2r[4][2], b2r[4][2];
#pragma unroll
    for (int nt = 0; nt < 4; nt++) {
        int col = zcls * 256 + wn * 32 + nt * 8 + 2 * t;
        b1r[nt][0] = __ldg(b1 + col);
        b1r[nt][1] = __ldg(b1 + col + 1);
        int h = wn * 32 + nt * 8 + 2 * t;
        w2r[nt][0] = __ldg(n2w + h);  w2r[nt][1] = __ldg(n2w + h + 1);
        b2r[nt][0] = __ldg(n2b + h);  b2r[nt][1] = __ldg(n2b + h + 1);
    }

    u32* zout = zcls ? z2out : z1out;

    // ---- prefetch first tile's x into sx
    {
        int tile0 = bidc;
        if (tile0 < ntiles) {
            const float4* src = (const float4*)(x + (size_t)tile0 * 32 * DDIM);
#pragma unroll
            for (int q = 0; q < 2; q++) {
                int i = q * 512 + tid;
                int r = i >> 5, j = i & 31;
                cp16(s2u(sx) + (u32)((r * 132 + j * 4) * 4), src + r * 32 + j);
            }
        }
        cp_commit();
    }
    __syncthreads();

    for (int tile = bidc; tile < ntiles; tile += nblk) {
        const int row0 = tile * 32;
        if (zcls && tid < 32) ssg[tid] = __ldg(seg + row0 + tid);

        cp_wait0();
        __syncthreads();

        // ---- LN1 from sx -> sa (each warp: 2 rows)
#pragma unroll
        for (int rr = 0; rr < 2; rr++) {
            int rl = wid * 2 + rr;
            float4 xv = *(const float4*)&sx[rl * 132 + lane * 4];
            float s  = warp_sum(xv.x + xv.y + xv.z + xv.w);
            float sq = warp_sum(xv.x * xv.x + xv.y * xv.y + xv.z * xv.z + xv.w * xv.w);
            float m = s * (1.f / 128.f);
            float inv = rsqrtf(sq * (1.f / 128.f) - m * m + LN_EPS);
            float y0 = (xv.x - m) * inv * wv.x + bv.x;
            float y1 = (xv.y - m) * inv * wv.y + bv.y;
            float y2 = (xv.z - m) * inv * wv.z + bv.z;
            float y3 = (xv.w - m) * inv * wv.w + bv.w;
            *(uint2*)(sa + rl * 68 + lane * 2) = make_uint2(pkbf(y0, y1), pkbf(y2, y3));
        }
        __syncthreads();

        // ---- issue cp.async for next tile (lands during GEMM) +
        //      L2 prefetch at distance 2 (so next cp.async fills from L2)
        {
            int nxt = tile + nblk;
            if (nxt < ntiles) {
                const float4* src = (const float4*)(x + (size_t)nxt * 32 * DDIM);
#pragma unroll
                for (int q = 0; q < 2; q++) {
                    int i = q * 512 + tid;
                    int r = i >> 5, j = i & 31;
                    cp16(s2u(sx) + (u32)((r * 132 + j * 4) * 4), src + r * 32 + j);
                }
            }
            cp_commit();
            int nxt2 = tile + 2 * nblk;
            if (nxt2 < ntiles && tid < 128) {
                // 32 rows x 512B = 16 KB = 128 lines of 128B
                pf_l2(x + (size_t)nxt2 * 32 * DDIM + (size_t)tid * 32);
            }
        }

        // ---- GEMM: 32 rows x 256 cols (this class's half), K=128
        float acc[4][4];
#pragma unroll
        for (int nt = 0; nt < 4; nt++)
#pragma unroll
            for (int j = 0; j < 4; j++) acc[nt][j] = 0.f;

#pragma unroll
        for (int k0 = 0; k0 < 128; k0 += 16) {
            const int kp = k0 >> 1;
            u32 a[4];
            const u32* pa = sa + (wm * 16 + g) * 68 + kp + t;
            a[0] = pa[0];
            a[2] = pa[4];
            a[1] = pa[8 * 68];
            a[3] = pa[8 * 68 + 4];
#pragma unroll
            for (int nt = 0; nt < 4; nt++) {
                const u32* pb = sw + (wn * 32 + nt * 8 + g) * 68 + kp + t;
                mma_bf16(acc[nt], a, pb[0], pb[4]);
            }
        }

        // ---- bias + SELU (MUFU-free)
#pragma unroll
        for (int nt = 0; nt < 4; nt++) {
            acc[nt][0] = selu_f(acc[nt][0] + b1r[nt][0]);
            acc[nt][1] = selu_f(acc[nt][1] + b1r[nt][1]);
            acc[nt][2] = selu_f(acc[nt][2] + b1r[nt][0]);
            acc[nt][3] = selu_f(acc[nt][3] + b1r[nt][1]);
        }

        if (zcls == 0) {
            // ---- z1: pack to sz, flush coalesced as uint4
#pragma unroll
            for (int nt = 0; nt < 4; nt++) {
                int r = wm * 16 + g;
                int c2 = wn * 16 + nt * 4 + t;
                sz[r * 132 + c2]       = pkbf(acc[nt][0], acc[nt][1]);
                sz[(r + 8) * 132 + c2] = pkbf(acc[nt][2], acc[nt][3]);
            }
            __syncthreads();
#pragma unroll
            for (int q = 0; q < 2; q++) {
                int i = q * 512 + tid;          // 0..1023
                int r = i >> 5, c4 = i & 31;
                ((uint4*)zout)[((size_t)(row0 + r) << 5) + c4] =
                    *(const uint4*)&sz[r * 132 + c4 * 4];
            }
        } else {
            // ---- z2: LN2, pack, flush, segsum
            float s[2], q[2];
            s[0] = s[1] = q[0] = q[1] = 0.f;
#pragma unroll
            for (int nt = 0; nt < 4; nt++) {
                s[0] += acc[nt][0] + acc[nt][1];
                q[0] += acc[nt][0] * acc[nt][0] + acc[nt][1] * acc[nt][1];
                s[1] += acc[nt][2] + acc[nt][3];
                q[1] += acc[nt][2] * acc[nt][2] + acc[nt][3] * acc[nt][3];
            }
#pragma unroll
            for (int off = 1; off <= 2; off <<= 1)
#pragma unroll
                for (int h = 0; h < 2; h++) {
                    s[h] += __shfl_xor_sync(0xffffffffu, s[h], off);
                    q[h] += __shfl_xor_sync(0xffffffffu, q[h], off);
                }
            if (t == 0) {
#pragma unroll
                for (int h = 0; h < 2; h++) {
                    int r = wm * 16 + g + 8 * h;
                    ps[r * 8 + wn] = s[h];
                    pq[r * 8 + wn] = q[h];
                }
            }
            __syncthreads();
            float mean[2], inv[2];
#pragma unroll
            for (int h = 0; h < 2; h++) {
                int r = wm * 16 + g + 8 * h;
                float S = 0.f, Q = 0.f;
#pragma unroll
                for (int w = 0; w < 8; w++) { S += ps[r * 8 + w]; Q += pq[r * 8 + w]; }
                float m = S * (1.f / 256.f);
                mean[h] = m;
                inv[h] = rsqrtf(Q * (1.f / 256.f) - m * m + LN_EPS);
            }
#pragma unroll
            for (int nt = 0; nt < 4; nt++) {
                int r = wm * 16 + g;
                int c2 = wn * 16 + nt * 4 + t;
                float y0 = (acc[nt][0] - mean[0]) * inv[0] * w2r[nt][0] + b2r[nt][0];
                float y1 = (acc[nt][1] - mean[0]) * inv[0] * w2r[nt][1] + b2r[nt][1];
                float y2 = (acc[nt][2] - mean[1]) * inv[1] * w2r[nt][0] + b2r[nt][0];
                float y3 = (acc[nt][3] - mean[1]) * inv[1] * w2r[nt][1] + b2r[nt][1];
                sz[r * 132 + c2]       = pkbf(y0, y1);
                sz[(r + 8) * 132 + c2] = pkbf(y2, y3);
            }
            __syncthreads();
#pragma unroll
            for (int q2 = 0; q2 < 2; q2++) {
                int i = q2 * 512 + tid;
                int r = i >> 5, c4 = i & 31;
                ((uint4*)zout)[((size_t)(row0 + r) << 5) + c4] =
                    *(const uint4*)&sz[r * 132 + c4 * 4];
            }

            // run-length aggregated segment sums (segs sorted)
            {
                int grp = tid >> 8;
                int col = tid & 255;
                int rb = grp * 16;
                float accv = 0.f, cnt = 0.f;
                int cur = ssg[rb];
#pragma unroll 1
                for (int r = rb; r < rb + 16; r++) {
                    int sv = ssg[r];
                    if (sv != cur) {
                        atomicAdd(&segsum[(size_t)cur * HDIM + col], accv);
                        if (col == 0) atomicAdd(&segcnt[cur], cnt);
                        accv = 0.f; cnt = 0.f; cur = sv;
                    }
                    float2 pv = upbf(sz[r * 132 + (col >> 1)]);
                    accv += (col & 1) ? pv.y : pv.x;
                    cnt += 1.f;
                }
                atomicAdd(&segsum[(size_t)cur * HDIM + col], accv);
                if (col == 0) atomicAdd(&segcnt[cur], cnt);
            }
        }
        __syncthreads();
    }
}

// ---------------- Kernel 2: gate coefficients + zero-after-read -----------
__global__ void coeff_kernel(float* __restrict__ sum_r, float* __restrict__ cnt_r,
                             float* __restrict__ sum_a, float* __restrict__ cnt_a,
                             const float* __restrict__ ref_reg, const float* __restrict__ reg_w_pre,
                             const float* __restrict__ beta_ref, const float* __restrict__ beta_alt,
                             const float* __restrict__ gamma,
                             float* __restrict__ cref, float* __restrict__ calt) {
    int b = blockIdx.x;
    int h = threadIdx.x;
    float rw = expf(reg_w_pre[0]) + 0.25f;
    float rcr = 1.f / (__ldg(cnt_r + b) + rw);
    float rca = 1.f / fmaxf(__ldg(cnt_a + b), 1.f);
    int idx = (b << 8) + h;
    float rmf = (__ldg(sum_r + idx) + rw * __ldg(ref_reg + h)) * rcr;
    float amf = __ldg(sum_a + idx) * rca;
    cref[idx] = beta_ref[0] * rmf;
    calt[idx] = beta_alt[0] * amf + gamma[0] * rmf;
    __syncthreads();               // all reads of cnt/sum done before re-zero
    sum_r[idx] = 0.f;
    sum_a[idx] = 0.f;
    if (h == 0) { cnt_r[b] = 0.f; cnt_a[b] = 0.f; }
}

// ---------------- Kernel 3: persistent gate+GEMM2+residual ----------------
// 512 threads, 2 CTA/SM. W2 bf16 resident. Tile = 64 rows. Warp tile m16n32.
// Gate-build uint4 wide; epilogue staged through sg, coalesced float4 out.
// L2 prefetch (z1/z2/x + ctab rows) issued at tile START for max lead time.
#define SW2_U (128 * 132)
#define SG_U  (64 * 132)
#define SM2_BYTES ((SW2_U + SG_U) * 4 + 64 * 4)

__global__ void __launch_bounds__(512, 2)
fwd2_kernel(const float* __restrict__ x, const int* __restrict__ seg,
            const u32* __restrict__ z1, const u32* __restrict__ z2,
            const float* __restrict__ ctab, const float* __restrict__ alpha_p,
            const float* __restrict__ w2, const float* __restrict__ b2,
            float* __restrict__ out, int ntiles) {
    extern __shared__ float smf[];
    u32* sw = (u32*)smf;            // [128 n][132] bf16 k-pairs of W2
    u32* sg = sw + SW2_U;           // [64 m][132]  gated acts / f32 out staging
    int* ssg = (int*)(sg + SG_U);   // [64]

    const int tid = threadIdx.x;
    const int lane = tid & 31;
    const int wid = tid >> 5;
    const int g = lane >> 2;
    const int t = lane & 3;
    const int wm = wid & 3;    // 4 row-groups of 16
    const int wn = wid >> 2;   // 4 col-groups of 32

    for (int i = tid; i < 128 * 128; i += 512) {
        int kp = i >> 7;
        int n = i & 127;
        float v0 = __ldg(w2 + (size_t)(2 * kp) * DDIM + n);
        float v1 = __ldg(w2 + (size_t)(2 * kp + 1) * DDIM + n);
        sw[n * 132 + kp] = pkbf(v0, v1);
    }
    float b2r[4][2];
#pragma unroll
    for (int nt = 0; nt < 4; nt++) {
        int col = wn * 32 + nt * 8 + 2 * t;
        b2r[nt][0] = __ldg(b2 + col);
        b2r[nt][1] = __ldg(b2 + col + 1);
    }
    const float alpha = __ldg(alpha_p);
    __syncthreads();

    const uint4* z1v4 = (const uint4*)z1;
    const uint4* z2v4 = (const uint4*)z2;
    const float4* ctab4 = (const float4*)ctab;
    const float4* x4 = (const float4*)x;
    float4* out4 = (float4*)out;
    float* sgf = (float*)sg;

    for (int tile = blockIdx.x; tile < ntiles; tile += gridDim.x) {
        const int row0 = tile * 64;
        if (tid < 64) ssg[tid] = __ldg(seg + row0 + tid);

        // ---- L2-prefetch next tile's z1/z2/x + ctab rows (max lead time)
        {
            int nxt = tile + gridDim.x;
            if (nxt < ntiles) {
                if (tid < 256) {
                    size_t u4 = (size_t)nxt * 2048 + (size_t)tid * 8;
                    pf_l2(z1v4 + u4);
                    pf_l2(z2v4 + u4);
                } else {
                    size_t u4 = (size_t)nxt * 2048 + (size_t)(tid - 256) * 8;
                    pf_l2(x4 + u4);
                }
                if (tid < 64) {
                    int nsv = __ldg(seg + nxt * 64 + tid);
                    const char* crow = (const char*)(ctab + ((size_t)nsv << 8));
#pragma unroll
                    for (int l = 0; l < 8; l++) pf_l2(crow + l * 128);
                }
            }
        }
        __syncthreads();

        // gate-build, uint4 wide: 4 iterations, each thread covers 8 columns
#pragma unroll
        for (int q = 0; q < 4; q++) {
            int i = q * 512 + tid;              // 0..2047
            int r = i >> 5, c4 = i & 31;        // row, uint4-index (32/row)
            size_t gidx = ((size_t)(row0 + r) << 5) + c4;
            uint4 z1q = __ldg(z1v4 + gidx);
            uint4 z2q = __ldg(z2v4 + gidx);
            const float4* cp4 = ctab4 + (((size_t)ssg[r]) << 6) + c4 * 2;
            float4 ca = __ldg(cp4);
            float4 cb = __ldg(cp4 + 1);
            float2 p0 = upbf(z1q.x), p1 = upbf(z1q.y), p2 = upbf(z1q.z), p3 = upbf(z1q.w);
            float2 q0 = upbf(z2q.x), q1 = upbf(z2q.y), q2 = upbf(z2q.z), q3 = upbf(z2q.w);
            uint4 o;
            o.x = pkbf(p0.x * fmaf(q0.x, alpha, 1.f + ca.x),
                       p0.y * fmaf(q0.y, alpha, 1.f + ca.y));
            o.y = pkbf(p1.x * fmaf(q1.x, alpha, 1.f + ca.z),
                       p1.y * fmaf(q1.y, alpha, 1.f + ca.w));
            o.z = pkbf(p2.x * fmaf(q2.x, alpha, 1.f + cb.x),
                       p2.y * fmaf(q2.y, alpha, 1.f + cb.y));
            o.w = pkbf(p3.x * fmaf(q3.x, alpha, 1.f + cb.z),
                       p3.y * fmaf(q3.y, alpha, 1.f + cb.w));
            *(uint4*)&sg[r * 132 + c4 * 4] = o;
        }
        __syncthreads();

        float acc[4][4];
#pragma unroll
        for (int nt = 0; nt < 4; nt++)
#pragma unroll
            for (int j = 0; j < 4; j++) acc[nt][j] = 0.f;

#pragma unroll
        for (int k0 = 0; k0 < 256; k0 += 16) {
            const int kp = k0 >> 1;
            u32 a[4];
            const u32* pa = sg + (wm * 16 + g) * 132 + kp + t;
            a[0] = pa[0];
            a[2] = pa[4];
            a[1] = pa[8 * 132];
            a[3] = pa[8 * 132 + 4];
#pragma unroll
            for (int nt = 0; nt < 4; nt++) {
                const u32* pb = sw + (wn * 32 + nt * 8 + g) * 132 + kp + t;
                mma_bf16(acc[nt], a, pb[0], pb[4]);
            }
        }
        __syncthreads();   // all A-fragment reads of sg done -> reuse as f32

        // stage acc+bias into sg (f32), rows stride 132
#pragma unroll
        for (int nt = 0; nt < 4; nt++) {
            int col = wn * 32 + nt * 8 + 2 * t;
            int rA = wm * 16 + g;
            sgf[rA * 132 + col]           = acc[nt][0] + b2r[nt][0];
            sgf[rA * 132 + col + 1]       = acc[nt][1] + b2r[nt][1];
            sgf[(rA + 8) * 132 + col]     = acc[nt][2] + b2r[nt][0];
            sgf[(rA + 8) * 132 + col + 1] = acc[nt][3] + b2r[nt][1];
        }
        __syncthreads();

        // coalesced residual + store: out = x + staged, float4 wide
#pragma unroll
        for (int q = 0; q < 4; q++) {
            int i = q * 512 + tid;              // 0..2047
            int r = i >> 5, c4 = i & 31;        // 32 float4 per row
            size_t gidx = ((size_t)(row0 + r) << 5) + c4;
            float4 xv = __ldg(x4 + gidx);
            float4 sv = *(const float4*)&sgf[r * 132 + c4 * 4];
            float4 ov;
            ov.x = xv.x + sv.x;
            ov.y = xv.y + sv.y;
            ov.z = xv.z + sv.z;
            ov.w = xv.w + sv.w;
            out4[gidx] = ov;
        }
        __syncthreads();
    }
}

// ---------------- Launch: fork/join ref∥alt on side stream ----------------
extern "C" void kernel_launch(void* const* d_in, const int* in_sizes, int n_in,
                              void* d_out, int out_size) {
    const float* ref_flat = (const float*)d_in[0];
    const float* alt_flat = (const float*)d_in[1];
    const int*   ref_seg  = (const int*)d_in[2];
    const int*   alt_seg  = (const int*)d_in[3];
    const float* norm1_w  = (const float*)d_in[4];
    const float* norm1_b  = (const float*)d_in[5];
    const float* w1_ref   = (const float*)d_in[6];
    const float* b1_ref   = (const float*)d_in[7];
    const float* w1_alt   = (const float*)d_in[8];
    const float* b1_alt   = (const float*)d_in[9];
    const float* norm2_w  = (const float*)d_in[10];
    const float* norm2_b  = (const float*)d_in[11];
    const float* alpha_ref = (const float*)d_in[12];
    const float* alpha_alt = (const float*)d_in[13];
    const float* beta_ref  = (const float*)d_in[14];
    const float* beta_alt  = (const float*)d_in[15];
    const float* gamma     = (const float*)d_in[16];
    const float* ref_regularizer = (const float*)d_in[17];
    const float* reg_w_pre = (const float*)d_in[18];
    const float* w2_ref    = (const float*)d_in[19];
    const float* b2_ref    = (const float*)d_in[20];
    const float* w2_alt    = (const float*)d_in[21];
    const float* b2_alt    = (const float*)d_in[22];

    float* out_r = (float*)d_out;
    float* out_a = out_r + (size_t)NREF * DDIM;

    u32 *pz1r, *pz2r, *pz1a, *pz2a;
    float *psr, *psa, *pcr, *pca, *pcref, *pcalt;
    cudaGetSymbolAddress((void**)&pz1r, g_z1_ref);
    cudaGetSymbolAddress((void**)&pz2r, g_z2_ref);
    cudaGetSymbolAddress((void**)&pz1a, g_z1_alt);
    cudaGetSymbolAddress((void**)&pz2a, g_z2_alt);
    cudaGetSymbolAddress((void**)&psr,  g_sum_ref);
    cudaGetSymbolAddress((void**)&psa,  g_sum_alt);
    cudaGetSymbolAddress((void**)&pcr,  g_cnt_ref);
    cudaGetSymbolAddress((void**)&pca,  g_cnt_alt);
    cudaGetSymbolAddress((void**)&pcref, g_cref);
    cudaGetSymbolAddress((void**)&pcalt, g_calt);

    int sm_count = 148;
    cudaDeviceGetAttribute(&sm_count, cudaDevAttrMultiProcessorCount, 0);

    cudaFuncSetAttribute(fwd1_kernel, cudaFuncAttributeMaxDynamicSharedMemorySize, SM1_BYTES);
    cudaFuncSetAttribute(fwd2_kernel, cudaFuncAttributeMaxDynamicSharedMemorySize, SM2_BYTES);

    // side stream + events for ref||alt overlap (fork/join, graph-capturable)
    cudaStream_t s1;
    cudaStreamCreateWithFlags(&s1, cudaStreamNonBlocking);
    cudaEvent_t eFork1, eJoin1, eFork2, eJoin2;
    cudaEventCreateWithFlags(&eFork1, cudaEventDisableTiming);
    cudaEventCreateWithFlags(&eJoin1, cudaEventDisableTiming);
    cudaEventCreateWithFlags(&eFork2, cudaEventDisableTiming);
    cudaEventCreateWithFlags(&eJoin2, cudaEventDisableTiming);

    // ---- stage 1: fwd1 ref (stream 0) || fwd1 alt (s1)
    cudaEventRecord(eFork1, 0);
    cudaStreamWaitEvent(s1, eFork1, 0);
    fwd1_kernel<<<2 * sm_count, 512, SM1_BYTES>>>(ref_flat, ref_seg, norm1_w, norm1_b,
                                                  w1_ref, b1_ref, norm2_w, norm2_b,
                                                  pz1r, pz2r, psr, pcr, NREF / 32);
    fwd1_kernel<<<2 * sm_count, 512, SM1_BYTES, s1>>>(alt_flat, alt_seg, norm1_w, norm1_b,
                                                      w1_alt, b1_alt, norm2_w, norm2_b,
                                                      pz1a, pz2a, psa, pca, NALT / 32);
    cudaEventRecord(eJoin1, s1);
    cudaStreamWaitEvent(0, eJoin1, 0);

    // ---- stage 2: coefficients (depends on both fwd1)
    coeff_kernel<<<BSEG, 256>>>(psr, pcr, psa, pca,
                                ref_regularizer, reg_w_pre,
                                beta_ref, beta_alt, gamma,
                                pcref, pcalt);

    // ---- stage 3: fwd2 ref (stream 0) || fwd2 alt (s1)
    cudaEventRecord(eFork2, 0);
    cudaStreamWaitEvent(s1, eFork2, 0);
    fwd2_kernel<<<2 * sm_count, 512, SM2_BYTES>>>(ref_flat, ref_seg, pz1r, pz2r,
                                                  pcref, alpha_ref, w2_ref, b2_ref,
                                                  out_r, NREF / 64);
    fwd2_kernel<<<2 * sm_count, 512, SM2_BYTES, s1>>>(alt_flat, alt_seg, pz1a, pz2a,
                                                      pcalt, alpha_alt, w2_alt, b2_alt,
                                                      out_a, NALT / 64);
    cudaEventRecord(eJoin2, s1);
    cudaStreamWaitEvent(0, eJoin2, 0);

    cudaEventDestroy(eFork1);
    cudaEventDestroy(eJoin1);
    cudaEventDestroy(eFork2);
    cudaEventDestroy(eJoin2);
    cudaStreamDestroy(s1);
}

// round 17
// speedup vs baseline: 1.0327x; 1.0327x over previous
#include <cuda_runtime.h>
#include <cuda_bf16.h>
#include <math.h>

// ---------------- Problem constants ----------------
#define NREF 131072
#define NALT 32768
#define BSEG 4096
#define DDIM 128
#define FDIM 512
#define HDIM 256
#define LN_EPS 1e-5f

typedef unsigned int u32;

// ---------------- Scratch (device globals) ----------------
__device__ u32 g_z1_ref[(size_t)NREF * 128];   // bf16x2 pairs (256 cols)
__device__ u32 g_z2_ref[(size_t)NREF * 128];
__device__ u32 g_z1_alt[(size_t)NALT * 128];
__device__ u32 g_z2_alt[(size_t)NALT * 128];
__device__ float g_sum_ref[BSEG * HDIM];       // zero-init at load; coeff re-zeros
__device__ float g_sum_alt[BSEG * HDIM];
__device__ float g_cnt_ref[BSEG];
__device__ float g_cnt_alt[BSEG];
__device__ float g_cref[BSEG * HDIM];
__device__ float g_calt[BSEG * HDIM];

// ---------------- Helpers ----------------
__device__ __forceinline__ u32 pkbf(float lo, float hi) {
    u32 r;
    asm("cvt.rn.bf16x2.f32 %0, %1, %2;" : "=r"(r) : "f"(hi), "f"(lo));
    return r;
}
__device__ __forceinline__ float2 upbf(u32 v) {
    union { u32 u; __nv_bfloat162 h; } cv;
    cv.u = v;
    return __bfloat1622float2(cv.h);
}
__device__ __forceinline__ void mma_bf16(float* c, const u32* a, u32 b0, u32 b1) {
    asm volatile(
        "mma.sync.aligned.m16n8k16.row.col.f32.bf16.bf16.f32 "
        "{%0,%1,%2,%3}, {%4,%5,%6,%7}, {%8,%9}, {%0,%1,%2,%3};"
        : "+f"(c[0]), "+f"(c[1]), "+f"(c[2]), "+f"(c[3])
        : "r"(a[0]), "r"(a[1]), "r"(a[2]), "r"(a[3]), "r"(b0), "r"(b1));
}
__device__ __forceinline__ u32 s2u(const void* p) {
    return (u32)__cvta_generic_to_shared(p);
}
__device__ __forceinline__ void cp16(u32 smem_dst, const void* gsrc) {
    asm volatile("cp.async.cg.shared.global [%0], [%1], 16;"
                 :: "r"(smem_dst), "l"(gsrc));
}
__device__ __forceinline__ void cp_commit() {
    asm volatile("cp.async.commit_group;");
}
__device__ __forceinline__ void cp_wait0() {
    asm volatile("cp.async.wait_group 0;");
}
__device__ __forceinline__ void pf_l2(const void* p) {
    asm volatile("prefetch.global.L2 [%0];" :: "l"(p));
}
__device__ __forceinline__ float warp_sum(float v) {
#pragma unroll
    for (int o = 16; o > 0; o >>= 1) v += __shfl_xor_sync(0xffffffffu, v, o);
    return v;
}

// SELU with MUFU-free exp: 2^t split (floor + degree-5 poly on FMA pipe +
// integer exponent reconstruction). Rel err ~1.5e-5 << bf16 rounding of z.
__device__ __forceinline__ float selu_f(float x) {
    const float sc = 1.0507009873554805f;
    const float al = 1.6732632423543772f;
    float t = fmaxf(x * 1.4426950408889634f, -126.0f);
    float fl = floorf(t);
    float f = t - fl;
    float p =            1.3333558146e-3f;
    p = fmaf(p, f, 9.6181291076e-3f);
    p = fmaf(p, f, 5.5504108664e-2f);
    p = fmaf(p, f, 2.4022650695e-1f);
    p = fmaf(p, f, 6.9314718056e-1f);
    p = fmaf(p, f, 1.0f);
    float e2 = __int_as_float(((int)fl + 127) << 23);
    float ex = p * e2;
    return x > 0.f ? sc * x : fmaf(sc * al, ex, -(sc * al));
}

// ---------------- Kernel 1: split-class persistent LN1+GEMM1 --------------
// 2 CTAs/SM. Even blocks: z1 half. Odd blocks: z2 half + LN2 + segsum.
// sz stride 132 (uint4-aligned flushes).
#define SW1_U (256 * 68)
#define SA_U  (32 * 68)
#define SZ_U  (32 * 132)
#define SX_U  (32 * 132)
#define SM1_BYTES ((SW1_U + SA_U + SZ_U + SX_U + 32 * 8 * 2) * 4 + 32 * 4)

__global__ void __launch_bounds__(512, 2)
fwd1_kernel(const float* __restrict__ x, const int* __restrict__ seg,
            const float* __restrict__ n1w, const float* __restrict__ n1b,
            const float* __restrict__ w1, const float* __restrict__ b1,
            const float* __restrict__ n2w, const float* __restrict__ n2b,
            u32* __restrict__ z1out, u32* __restrict__ z2out,
            float* __restrict__ segsum, float* __restrict__ segcnt,
            int ntiles) {
    extern __shared__ float smf[];
    u32* sw = (u32*)smf;              // [256 n][68] bf16 k-pairs of W1 half
    u32* sa = sw + SW1_U;             // [32 m][68]  bf16 k-pairs of LN1(x)
    u32* sz = sa + SA_U;              // [32 m][132] bf16 col-pairs staging
    float* sx = (float*)(sz + SZ_U);  // [32 m][132] prefetched x (f32)
    float* ps = sx + SX_U;            // [32][8] LN2 partial sums
    float* pq = ps + 32 * 8;          // [32][8] LN2 partial sumsq
    int*   ssg = (int*)(pq + 32 * 8); // [32]

    const int zcls = blockIdx.x & 1;       // 0 -> z1 half, 1 -> z2 half
    const int bidc = blockIdx.x >> 1;
    const int nblk = gridDim.x >> 1;

    const int tid = threadIdx.x;
    const int lane = tid & 31;
    const int wid = tid >> 5;
    const int g = lane >> 2;
    const int t = lane & 3;
    const int wm = wid & 1;    // 2 row-groups of 16
    const int wn = wid >> 1;   // 8 col-groups of 32

    // ---- stage this class's W1 half (f32 gmem -> bf16-pair smem), once
    for (int i = tid; i < 64 * 256; i += 512) {
        int kp = i >> 8;
        int n = i & 255;
        float v0 = __ldg(w1 + (size_t)(2 * kp) * FDIM + zcls * 256 + n);
        float v1 = __ldg(w1 + (size_t)(2 * kp + 1) * FDIM + zcls * 256 + n);
        sw[n * 68 + kp] = pkbf(v0, v1);
    }

    // ---- hoist per-thread constants
    float4 wv = __ldg(((const float4*)n1w) + lane);
    float4 bv = __ldg(((const float4*)n1b) + lane);
    float b1r[4][2], w2r[4][2], b2r[4][2];
#pragma unroll
    for (int nt = 0; nt < 4; nt++) {
        int col = zcls * 256 + wn * 32 + nt * 8 + 2 * t;
        b1r[nt][0] = __ldg(b1 + col);
        b1r[nt][1] = __ldg(b1 + col + 1);
        int h = wn * 32 + nt * 8 + 2 * t;
        w2r[nt][0] = __ldg(n2w + h);  w2r[nt][1] = __ldg(n2w + h + 1);
        b2r[nt][0] = __ldg(n2b + h);  b2r[nt][1] = __ldg(n2b + h + 1);
    }

    u32* zout = zcls ? z2out : z1out;

    // ---- prefetch first tile's x into sx
    {
        int tile0 = bidc;
        if (tile0 < ntiles) {
            const float4* src = (const float4*)(x + (size_t)tile0 * 32 * DDIM);
#pragma unroll
            for (int q = 0; q < 2; q++) {
                int i = q * 512 + tid;
                int r = i >> 5, j = i & 31;
                cp16(s2u(sx) + (u32)((r * 132 + j * 4) * 4), src + r * 32 + j);
            }
        }
        cp_commit();
    }
    __syncthreads();

    for (int tile = bidc; tile < ntiles; tile += nblk) {
        const int row0 = tile * 32;
        if (zcls && tid < 32) ssg[tid] = __ldg(seg + row0 + tid);

        cp_wait0();
        __syncthreads();

        // ---- LN1 from sx -> sa (each warp: 2 rows)
#pragma unroll
        for (int rr = 0; rr < 2; rr++) {
            int rl = wid * 2 + rr;
            float4 xv = *(const float4*)&sx[rl * 132 + lane * 4];
            float s  = warp_sum(xv.x + xv.y + xv.z + xv.w);
            float sq = warp_sum(xv.x * xv.x + xv.y * xv.y + xv.z * xv.z + xv.w * xv.w);
            float m = s * (1.f / 128.f);
            float inv = rsqrtf(sq * (1.f / 128.f) - m * m + LN_EPS);
            float y0 = (xv.x - m) * inv * wv.x + bv.x;
            float y1 = (xv.y - m) * inv * wv.y + bv.y;
            float y2 = (xv.z - m) * inv * wv.z + bv.z;
            float y3 = (xv.w - m) * inv * wv.w + bv.w;
            *(uint2*)(sa + rl * 68 + lane * 2) = make_uint2(pkbf(y0, y1), pkbf(y2, y3));
        }
        __syncthreads();

        // ---- issue prefetch for next tile (lands during GEMM)
        {
            int nxt = tile + nblk;
            if (nxt < ntiles) {
                const float4* src = (const float4*)(x + (size_t)nxt * 32 * DDIM);
#pragma unroll
                for (int q = 0; q < 2; q++) {
                    int i = q * 512 + tid;
                    int r = i >> 5, j = i & 31;
                    cp16(s2u(sx) + (u32)((r * 132 + j * 4) * 4), src + r * 32 + j);
                }
            }
            cp_commit();
        }

        // ---- GEMM: 32 rows x 256 cols (this class's half), K=128
        float acc[4][4];
#pragma unroll
        for (int nt = 0; nt < 4; nt++)
#pragma unroll
            for (int j = 0; j < 4; j++) acc[nt][j] = 0.f;

#pragma unroll
        for (int k0 = 0; k0 < 128; k0 += 16) {
            const int kp = k0 >> 1;
            u32 a[4];
            const u32* pa = sa + (wm * 16 + g) * 68 + kp + t;
            a[0] = pa[0];
            a[2] = pa[4];
            a[1] = pa[8 * 68];
            a[3] = pa[8 * 68 + 4];
#pragma unroll
            for (int nt = 0; nt < 4; nt++) {
                const u32* pb = sw + (wn * 32 + nt * 8 + g) * 68 + kp + t;
                mma_bf16(acc[nt], a, pb[0], pb[4]);
            }
        }

        // ---- bias + SELU (MUFU-free)
#pragma unroll
        for (int nt = 0; nt < 4; nt++) {
            acc[nt][0] = selu_f(acc[nt][0] + b1r[nt][0]);
            acc[nt][1] = selu_f(acc[nt][1] + b1r[nt][1]);
            acc[nt][2] = selu_f(acc[nt][2] + b1r[nt][0]);
            acc[nt][3] = selu_f(acc[nt][3] + b1r[nt][1]);
        }

        if (zcls == 0) {
            // ---- z1: pack to sz, flush coalesced as uint4
#pragma unroll
            for (int nt = 0; nt < 4; nt++) {
                int r = wm * 16 + g;
                int c2 = wn * 16 + nt * 4 + t;
                sz[r * 132 + c2]       = pkbf(acc[nt][0], acc[nt][1]);
                sz[(r + 8) * 132 + c2] = pkbf(acc[nt][2], acc[nt][3]);
            }
            __syncthreads();
#pragma unroll
            for (int q = 0; q < 2; q++) {
                int i = q * 512 + tid;          // 0..1023
                int r = i >> 5, c4 = i & 31;
                ((uint4*)zout)[((size_t)(row0 + r) << 5) + c4] =
                    *(const uint4*)&sz[r * 132 + c4 * 4];
            }
        } else {
            // ---- z2: LN2, pack, flush, segsum
            float s[2], q[2];
            s[0] = s[1] = q[0] = q[1] = 0.f;
#pragma unroll
            for (int nt = 0; nt < 4; nt++) {
                s[0] += acc[nt][0] + acc[nt][1];
                q[0] += acc[nt][0] * acc[nt][0] + acc[nt][1] * acc[nt][1];
                s[1] += acc[nt][2] + acc[nt][3];
                q[1] += acc[nt][2] * acc[nt][2] + acc[nt][3] * acc[nt][3];
            }
#pragma unroll
            for (int off = 1; off <= 2; off <<= 1)
#pragma unroll
                for (int h = 0; h < 2; h++) {
                    s[h] += __shfl_xor_sync(0xffffffffu, s[h], off);
                    q[h] += __shfl_xor_sync(0xffffffffu, q[h], off);
                }
            if (t == 0) {
#pragma unroll
                for (int h = 0; h < 2; h++) {
                    int r = wm * 16 + g + 8 * h;
                    ps[r * 8 + wn] = s[h];
                    pq[r * 8 + wn] = q[h];
                }
            }
            __syncthreads();
            float mean[2], inv[2];
#pragma unroll
            for (int h = 0; h < 2; h++) {
                int r = wm * 16 + g + 8 * h;
                float S = 0.f, Q = 0.f;
#pragma unroll
                for (int w = 0; w < 8; w++) { S += ps[r * 8 + w]; Q += pq[r * 8 + w]; }
                float m = S * (1.f / 256.f);
                mean[h] = m;
                inv[h] = rsqrtf(Q * (1.f / 256.f) - m * m + LN_EPS);
            }
#pragma unroll
            for (int nt = 0; nt < 4; nt++) {
                int r = wm * 16 + g;
                int c2 = wn * 16 + nt * 4 + t;
                float y0 = (acc[nt][0] - mean[0]) * inv[0] * w2r[nt][0] + b2r[nt][0];
                float y1 = (acc[nt][1] - mean[0]) * inv[0] * w2r[nt][1] + b2r[nt][1];
                float y2 = (acc[nt][2] - mean[1]) * inv[1] * w2r[nt][0] + b2r[nt][0];
                float y3 = (acc[nt][3] - mean[1]) * inv[1] * w2r[nt][1] + b2r[nt][1];
                sz[r * 132 + c2]       = pkbf(y0, y1);
                sz[(r + 8) * 132 + c2] = pkbf(y2, y3);
            }
            __syncthreads();
#pragma unroll
            for (int q2 = 0; q2 < 2; q2++) {
                int i = q2 * 512 + tid;
                int r = i >> 5, c4 = i & 31;
                ((uint4*)zout)[((size_t)(row0 + r) << 5) + c4] =
                    *(const uint4*)&sz[r * 132 + c4 * 4];
            }

            // run-length aggregated segment sums (segs sorted)
            {
                int grp = tid >> 8;
                int col = tid & 255;
                int rb = grp * 16;
                float accv = 0.f, cnt = 0.f;
                int cur = ssg[rb];
#pragma unroll 1
                for (int r = rb; r < rb + 16; r++) {
                    int sv = ssg[r];
                    if (sv != cur) {
                        atomicAdd(&segsum[(size_t)cur * HDIM + col], accv);
                        if (col == 0) atomicAdd(&segcnt[cur], cnt);
                        accv = 0.f; cnt = 0.f; cur = sv;
                    }
                    float2 pv = upbf(sz[r * 132 + (col >> 1)]);
                    accv += (col & 1) ? pv.y : pv.x;
                    cnt += 1.f;
                }
                atomicAdd(&segsum[(size_t)cur * HDIM + col], accv);
                if (col == 0) atomicAdd(&segcnt[cur], cnt);
            }
        }
        __syncthreads();
    }
}

// ---------------- Kernel 2: gate coefficients + zero-after-read -----------
__global__ void coeff_kernel(float* __restrict__ sum_r, float* __restrict__ cnt_r,
                             float* __restrict__ sum_a, float* __restrict__ cnt_a,
                             const float* __restrict__ ref_reg, const float* __restrict__ reg_w_pre,
                             const float* __restrict__ beta_ref, const float* __restrict__ beta_alt,
                             const float* __restrict__ gamma,
                             float* __restrict__ cref, float* __restrict__ calt) {
    int b = blockIdx.x;
    int h = threadIdx.x;
    float rw = expf(reg_w_pre[0]) + 0.25f;
    float rcr = 1.f / (__ldg(cnt_r + b) + rw);
    float rca = 1.f / fmaxf(__ldg(cnt_a + b), 1.f);
    int idx = (b << 8) + h;
    float rmf = (__ldg(sum_r + idx) + rw * __ldg(ref_reg + h)) * rcr;
    float amf = __ldg(sum_a + idx) * rca;
    cref[idx] = beta_ref[0] * rmf;
    calt[idx] = beta_alt[0] * amf + gamma[0] * rmf;
    __syncthreads();               // all reads of cnt/sum done before re-zero
    sum_r[idx] = 0.f;
    sum_a[idx] = 0.f;
    if (h == 0) { cnt_r[b] = 0.f; cnt_a[b] = 0.f; }
}

// ---------------- Kernel 3: persistent gate+GEMM2+residual ----------------
// 512 threads, 2 CTA/SM. W2 bf16 resident. Tile = 64 rows. Warp tile m16n32.
// Gate-build uint4 wide; epilogue staged through sg, coalesced float4 out.
// Next tile's z1/z2/x lines prefetched into L2 AFTER gate-build (R14 optimum).
#define SW2_U (128 * 132)
#define SG_U  (64 * 132)
#define SM2_BYTES ((SW2_U + SG_U) * 4 + 64 * 4)

__global__ void __launch_bounds__(512, 2)
fwd2_kernel(const float* __restrict__ x, const int* __restrict__ seg,
            const u32* __restrict__ z1, const u32* __restrict__ z2,
            const float* __restrict__ ctab, const float* __restrict__ alpha_p,
            const float* __restrict__ w2, const float* __restrict__ b2,
            float* __restrict__ out, int ntiles) {
    extern __shared__ float smf[];
    u32* sw = (u32*)smf;            // [128 n][132] bf16 k-pairs of W2
    u32* sg = sw + SW2_U;           // [64 m][132]  gated acts / f32 out staging
    int* ssg = (int*)(sg + SG_U);   // [64]

    const int tid = threadIdx.x;
    const int lane = tid & 31;
    const int wid = tid >> 5;
    const int g = lane >> 2;
    const int t = lane & 3;
    const int wm = wid & 3;    // 4 row-groups of 16
    const int wn = wid >> 2;   // 4 col-groups of 32

    for (int i = tid; i < 128 * 128; i += 512) {
        int kp = i >> 7;
        int n = i & 127;
        float v0 = __ldg(w2 + (size_t)(2 * kp) * DDIM + n);
        float v1 = __ldg(w2 + (size_t)(2 * kp + 1) * DDIM + n);
        sw[n * 132 + kp] = pkbf(v0, v1);
    }
    float b2r[4][2];
#pragma unroll
    for (int nt = 0; nt < 4; nt++) {
        int col = wn * 32 + nt * 8 + 2 * t;
        b2r[nt][0] = __ldg(b2 + col);
        b2r[nt][1] = __ldg(b2 + col + 1);
    }
    const float alpha = __ldg(alpha_p);
    __syncthreads();

    const uint4* z1v4 = (const uint4*)z1;
    const uint4* z2v4 = (const uint4*)z2;
    const float4* ctab4 = (const float4*)ctab;
    const float4* x4 = (const float4*)x;
    float4* out4 = (float4*)out;
    float* sgf = (float*)sg;

    for (int tile = blockIdx.x; tile < ntiles; tile += gridDim.x) {
        const int row0 = tile * 64;
        if (tid < 64) ssg[tid] = __ldg(seg + row0 + tid);
        __syncthreads();

        // gate-build, uint4 wide: 4 iterations, each thread covers 8 columns
#pragma unroll
        for (int q = 0; q < 4; q++) {
            int i = q * 512 + tid;              // 0..2047
            int r = i >> 5, c4 = i & 31;        // row, uint4-index (32/row)
            size_t gidx = ((size_t)(row0 + r) << 5) + c4;
            uint4 z1q = __ldg(z1v4 + gidx);
            uint4 z2q = __ldg(z2v4 + gidx);
            const float4* cp4 = ctab4 + (((size_t)ssg[r]) << 6) + c4 * 2;
            float4 ca = __ldg(cp4);
            float4 cb = __ldg(cp4 + 1);
            float2 p0 = upbf(z1q.x), p1 = upbf(z1q.y), p2 = upbf(z1q.z), p3 = upbf(z1q.w);
            float2 q0 = upbf(z2q.x), q1 = upbf(z2q.y), q2 = upbf(z2q.z), q3 = upbf(z2q.w);
            uint4 o;
            o.x = pkbf(p0.x * fmaf(q0.x, alpha, 1.f + ca.x),
                       p0.y * fmaf(q0.y, alpha, 1.f + ca.y));
            o.y = pkbf(p1.x * fmaf(q1.x, alpha, 1.f + ca.z),
                       p1.y * fmaf(q1.y, alpha, 1.f + ca.w));
            o.z = pkbf(p2.x * fmaf(q2.x, alpha, 1.f + cb.x),
                       p2.y * fmaf(q2.y, alpha, 1.f + cb.y));
            o.w = pkbf(p3.x * fmaf(q3.x, alpha, 1.f + cb.z),
                       p3.y * fmaf(q3.y, alpha, 1.f + cb.w));
            *(uint4*)&sg[r * 132 + c4 * 4] = o;
        }
        __syncthreads();

        // ---- L2-prefetch next tile's z1/z2/x (lands during GEMM)
        {
            int nxt = tile + gridDim.x;
            if (nxt < ntiles) {
                // per tile: z1,z2 = 2048 uint4 each = 256 lines of 128B;
                //           x     = 2048 float4    = 256 lines of 128B
                if (tid < 256) {
                    size_t u4 = (size_t)nxt * 2048 + (size_t)tid * 8;
                    pf_l2(z1v4 + u4);
                    pf_l2(z2v4 + u4);
                } else {
                    size_t u4 = (size_t)nxt * 2048 + (size_t)(tid - 256) * 8;
                    pf_l2(x4 + u4);
                }
            }
        }

        float acc[4][4];
#pragma unroll
        for (int nt = 0; nt < 4; nt++)
#pragma unroll
            for (int j = 0; j < 4; j++) acc[nt][j] = 0.f;

#pragma unroll
        for (int k0 = 0; k0 < 256; k0 += 16) {
            const int kp = k0 >> 1;
            u32 a[4];
            const u32* pa = sg + (wm * 16 + g) * 132 + kp + t;
            a[0] = pa[0];
            a[2] = pa[4];
            a[1] = pa[8 * 132];
            a[3] = pa[8 * 132 + 4];
#pragma unroll
            for (int nt = 0; nt < 4; nt++) {
                const u32* pb = sw + (wn * 32 + nt * 8 + g) * 132 + kp + t;
                mma_bf16(acc[nt], a, pb[0], pb[4]);
            }
        }
        __syncthreads();   // all A-fragment reads of sg done -> reuse as f32

        // stage acc+bias into sg (f32), rows stride 132
#pragma unroll
        for (int nt = 0; nt < 4; nt++) {
            int col = wn * 32 + nt * 8 + 2 * t;
            int rA = wm * 16 + g;
            sgf[rA * 132 + col]           = acc[nt][0] + b2r[nt][0];
            sgf[rA * 132 + col + 1]       = acc[nt][1] + b2r[nt][1];
            sgf[(rA + 8) * 132 + col]     = acc[nt][2] + b2r[nt][0];
            sgf[(rA + 8) * 132 + col + 1] = acc[nt][3] + b2r[nt][1];
        }
        __syncthreads();

        // coalesced residual + store: out = x + staged, float4 wide
#pragma unroll
        for (int q = 0; q < 4; q++) {
            int i = q * 512 + tid;              // 0..2047
            int r = i >> 5, c4 = i & 31;        // 32 float4 per row
            size_t gidx = ((size_t)(row0 + r) << 5) + c4;
            float4 xv = __ldg(x4 + gidx);
            float4 sv = *(const float4*)&sgf[r * 132 + c4 * 4];
            float4 ov;
            ov.x = xv.x + sv.x;
            ov.y = xv.y + sv.y;
            ov.z = xv.z + sv.z;
            ov.w = xv.w + sv.w;
            out4[gidx] = ov;
        }
        __syncthreads();
    }
}

// ---------------- Launch: fork/join ref∥alt on side stream ----------------
extern "C" void kernel_launch(void* const* d_in, const int* in_sizes, int n_in,
                              void* d_out, int out_size) {
    const float* ref_flat = (const float*)d_in[0];
    const float* alt_flat = (const float*)d_in[1];
    const int*   ref_seg  = (const int*)d_in[2];
    const int*   alt_seg  = (const int*)d_in[3];
    const float* norm1_w  = (const float*)d_in[4];
    const float* norm1_b  = (const float*)d_in[5];
    const float* w1_ref   = (const float*)d_in[6];
    const float* b1_ref   = (const float*)d_in[7];
    const float* w1_alt   = (const float*)d_in[8];
    const float* b1_alt   = (const float*)d_in[9];
    const float* norm2_w  = (const float*)d_in[10];
    const float* norm2_b  = (const float*)d_in[11];
    const float* alpha_ref = (const float*)d_in[12];
    const float* alpha_alt = (const float*)d_in[13];
    const float* beta_ref  = (const float*)d_in[14];
    const float* beta_alt  = (const float*)d_in[15];
    const float* gamma     = (const float*)d_in[16];
    const float* ref_regularizer = (const float*)d_in[17];
    const float* reg_w_pre = (const float*)d_in[18];
    const float* w2_ref    = (const float*)d_in[19];
    const float* b2_ref    = (const float*)d_in[20];
    const float* w2_alt    = (const float*)d_in[21];
    const float* b2_alt    = (const float*)d_in[22];

    float* out_r = (float*)d_out;
    float* out_a = out_r + (size_t)NREF * DDIM;

    u32 *pz1r, *pz2r, *pz1a, *pz2a;
    float *psr, *psa, *pcr, *pca, *pcref, *pcalt;
    cudaGetSymbolAddress((void**)&pz1r, g_z1_ref);
    cudaGetSymbolAddress((void**)&pz2r, g_z2_ref);
    cudaGetSymbolAddress((void**)&pz1a, g_z1_alt);
    cudaGetSymbolAddress((void**)&pz2a, g_z2_alt);
    cudaGetSymbolAddress((void**)&psr,  g_sum_ref);
    cudaGetSymbolAddress((void**)&psa,  g_sum_alt);
    cudaGetSymbolAddress((void**)&pcr,  g_cnt_ref);
    cudaGetSymbolAddress((void**)&pca,  g_cnt_alt);
    cudaGetSymbolAddress((void**)&pcref, g_cref);
    cudaGetSymbolAddress((void**)&pcalt, g_calt);

    int sm_count = 148;
    cudaDeviceGetAttribute(&sm_count, cudaDevAttrMultiProcessorCount, 0);

    cudaFuncSetAttribute(fwd1_kernel, cudaFuncAttributeMaxDynamicSharedMemorySize, SM1_BYTES);
    cudaFuncSetAttribute(fwd2_kernel, cudaFuncAttributeMaxDynamicSharedMemorySize, SM2_BYTES);

    // side stream + events for ref||alt overlap (fork/join, graph-capturable)
    cudaStream_t s1;
    cudaStreamCreateWithFlags(&s1, cudaStreamNonBlocking);
    cudaEvent_t eFork1, eJoin1, eFork2, eJoin2;
    cudaEventCreateWithFlags(&eFork1, cudaEventDisableTiming);
    cudaEventCreateWithFlags(&eJoin1, cudaEventDisableTiming);
    cudaEventCreateWithFlags(&eFork2, cudaEventDisableTiming);
    cudaEventCreateWithFlags(&eJoin2, cudaEventDisableTiming);

    // ---- stage 1: fwd1 ref (stream 0) || fwd1 alt (s1)
    cudaEventRecord(eFork1, 0);
    cudaStreamWaitEvent(s1, eFork1, 0);
    fwd1_kernel<<<2 * sm_count, 512, SM1_BYTES>>>(ref_flat, ref_seg, norm1_w, norm1_b,
                                                  w1_ref, b1_ref, norm2_w, norm2_b,
                                                  pz1r, pz2r, psr, pcr, NREF / 32);
    fwd1_kernel<<<2 * sm_count, 512, SM1_BYTES, s1>>>(alt_flat, alt_seg, norm1_w, norm1_b,
                                                      w1_alt, b1_alt, norm2_w, norm2_b,
                                                      pz1a, pz2a, psa, pca, NALT / 32);
    cudaEventRecord(eJoin1, s1);
    cudaStreamWaitEvent(0, eJoin1, 0);

    // ---- stage 2: coefficients (depends on both fwd1)
    coeff_kernel<<<BSEG, 256>>>(psr, pcr, psa, pca,
                                ref_regularizer, reg_w_pre,
                                beta_ref, beta_alt, gamma,
                                pcref, pcalt);

    // ---- stage 3: fwd2 ref (stream 0) || fwd2 alt (s1)
    cudaEventRecord(eFork2, 0);
    cudaStreamWaitEvent(s1, eFork2, 0);
    fwd2_kernel<<<2 * sm_count, 512, SM2_BYTES>>>(ref_flat, ref_seg, pz1r, pz2r,
                                                  pcref, alpha_ref, w2_ref, b2_ref,
                                                  out_r, NREF / 64);
    fwd2_kernel<<<2 * sm_count, 512, SM2_BYTES, s1>>>(alt_flat, alt_seg, pz1a, pz2a,
                                                      pcalt, alpha_alt, w2_alt, b2_alt,
                                                      out_a, NALT / 64);
    cudaEventRecord(eJoin2, s1);
    cudaStreamWaitEvent(0, eJoin2, 0);

    cudaEventDestroy(eFork1);
    cudaEventDestroy(eJoin1);
    cudaEventDestroy(eFork2);
    cudaEventDestroy(eJoin2);
    cudaStreamDestroy(s1);
}